// round 3
// baseline (speedup 1.0000x reference)
#include <cuda_runtime.h>
#include <cstdint>

#define N_NODES 100000
#define D_IN 128
#define D_HID 256
#define D_OUT 128
#define N_EDGES 1600000

// Scratch (static __device__ arrays — no runtime allocation).
__device__ float g_AX[(size_t)N_NODES * D_IN];   // 51.2 MB
__device__ float g_H [(size_t)N_NODES * D_HID];  // 102.4 MB

__device__ __forceinline__ float f2tf32(float f) {
    uint32_t r;
    asm("cvt.rna.tf32.f32 %0, %1;" : "=r"(r) : "f"(f));
    return __uint_as_float(r);
}

// ---------------------------------------------------------------------------
// K0: AX = (1 + eps) * x   (self-loop term, so scatter can accumulate on top)
// ---------------------------------------------------------------------------
__global__ void init_ax_kernel(const float* __restrict__ x,
                               const float* __restrict__ eps) {
    int i = blockIdx.x * blockDim.x + threadIdx.x;
    int n4 = N_NODES * D_IN / 4;
    if (i >= n4) return;
    float s = 1.0f + eps[0];
    float4 t = ((const float4*)x)[i];
    t.x *= s; t.y *= s; t.z *= s; t.w *= s;
    ((float4*)g_AX)[i] = t;
}

// ---------------------------------------------------------------------------
// K1: edge scatter. One warp per edge: 32 lanes x float4 = 128 floats.
// Vector atomics (red.global.add.v4.f32) quarter the L2 atomic op count.
// ---------------------------------------------------------------------------
__global__ void scatter_kernel(const float* __restrict__ x,
                               const float* __restrict__ ev,
                               const int* __restrict__ src,
                               const int* __restrict__ dst) {
    int gid  = blockIdx.x * blockDim.x + threadIdx.x;
    int eid  = gid >> 5;
    int lane = gid & 31;
    if (eid >= N_EDGES) return;
    int s = __ldg(src + eid);
    int d = __ldg(dst + eid);
    float v = __ldg(ev + eid);
    float4 t = *(const float4*)(x + (size_t)s * D_IN + lane * 4);
    t.x *= v; t.y *= v; t.z *= v; t.w *= v;
    float* o = g_AX + (size_t)d * D_IN + lane * 4;
    asm volatile("red.global.add.v4.f32 [%0], {%1,%2,%3,%4};"
                 :: "l"(o), "f"(t.x), "f"(t.y), "f"(t.z), "f"(t.w)
                 : "memory");
}

// ---------------------------------------------------------------------------
// K2/K3: tf32 tensor-core GEMM.
//   FIRST=true : g_H  = relu(g_AX @ W1 + b1)   (K=128, N=256)
//   FIRST=false: out  =       g_H @ W2 + b2    (K=256, N=128)
// Whole W tile (128 KB) lives in SMEM; A tile is BM=64 rows.
// 256 threads = 8 warps as 4(M) x 2(N); warp tile = 16 x N/2.
// SMEM padding: A stride = K+4 (== 4 mod 32), W stride = N+8 (== 8 mod 32)
// -> conflict-free fragment loads.
// ---------------------------------------------------------------------------
template<int K, int N, bool RELU, bool FIRST>
__global__ __launch_bounds__(256)
void gemm_kernel(const float* __restrict__ W,
                 const float* __restrict__ bias,
                 float* __restrict__ out_param, int M) {
    constexpr int BM = 64;
    constexpr int SA = K + 4;
    constexpr int SW = N + 8;
    constexpr int NT = N / 16;           // n-tiles of 8 per warp (warp covers N/2)

    extern __shared__ float sm[];
    float* As = sm;                      // BM x SA
    float* Ws = sm + BM * SA;            // K x SW

    const float* A  = FIRST ? g_AX : g_H;
    float*       out = FIRST ? g_H : out_param;

    const int tid = threadIdx.x;
    const int m0  = blockIdx.x * BM;

    // Stage W (convert to tf32 once).
    for (int i = tid; i < K * N / 4; i += 256) {
        int row = i / (N / 4);
        int c4  = (i % (N / 4)) * 4;
        float4 w = *(const float4*)(W + row * N + c4);
        float* p = Ws + row * SW + c4;
        p[0] = f2tf32(w.x); p[1] = f2tf32(w.y);
        p[2] = f2tf32(w.z); p[3] = f2tf32(w.w);
    }
    // Stage A tile.
    for (int i = tid; i < BM * K / 4; i += 256) {
        int row = i / (K / 4);
        int c4  = (i % (K / 4)) * 4;
        int gr  = m0 + row;
        float4 a = make_float4(0.f, 0.f, 0.f, 0.f);
        if (gr < M) a = *(const float4*)(A + (size_t)gr * K + c4);
        float* p = As + row * SA + c4;
        p[0] = f2tf32(a.x); p[1] = f2tf32(a.y);
        p[2] = f2tf32(a.z); p[3] = f2tf32(a.w);
    }
    __syncthreads();

    const int wid  = tid >> 5, lane = tid & 31;
    const int wm   = wid >> 1, wn   = wid & 1;
    const int g    = lane >> 2, tig = lane & 3;

    float c[NT][4];
#pragma unroll
    for (int i = 0; i < NT; i++) { c[i][0]=c[i][1]=c[i][2]=c[i][3]=0.f; }

    const int r0 = wm * 16 + g;
#pragma unroll 4
    for (int kk = 0; kk < K; kk += 8) {
        uint32_t a0 = __float_as_uint(As[ r0      * SA + kk     + tig]);
        uint32_t a1 = __float_as_uint(As[(r0 + 8) * SA + kk     + tig]);
        uint32_t a2 = __float_as_uint(As[ r0      * SA + kk + 4 + tig]);
        uint32_t a3 = __float_as_uint(As[(r0 + 8) * SA + kk + 4 + tig]);
#pragma unroll
        for (int nt = 0; nt < NT; nt++) {
            int col = wn * (N / 2) + nt * 8 + g;
            uint32_t b0 = __float_as_uint(Ws[(kk     + tig) * SW + col]);
            uint32_t b1 = __float_as_uint(Ws[(kk + 4 + tig) * SW + col]);
            asm volatile(
                "mma.sync.aligned.m16n8k8.row.col.f32.tf32.tf32.f32 "
                "{%0,%1,%2,%3}, {%4,%5,%6,%7}, {%8,%9}, {%0,%1,%2,%3};"
                : "+f"(c[nt][0]), "+f"(c[nt][1]), "+f"(c[nt][2]), "+f"(c[nt][3])
                : "r"(a0), "r"(a1), "r"(a2), "r"(a3), "r"(b0), "r"(b1));
        }
    }

    // Epilogue: bias (+ relu), float2 stores.
    const int gr0 = m0 + wm * 16 + g;
#pragma unroll
    for (int nt = 0; nt < NT; nt++) {
        int col = wn * (N / 2) + nt * 8 + 2 * tig;
        float bx = __ldg(bias + col), by = __ldg(bias + col + 1);
        float v0 = c[nt][0] + bx, v1 = c[nt][1] + by;
        float v2 = c[nt][2] + bx, v3 = c[nt][3] + by;
        if (RELU) {
            v0 = fmaxf(v0, 0.f); v1 = fmaxf(v1, 0.f);
            v2 = fmaxf(v2, 0.f); v3 = fmaxf(v3, 0.f);
        }
        if (gr0 < M)
            *(float2*)(out + (size_t)gr0 * N + col) = make_float2(v0, v1);
        if (gr0 + 8 < M)
            *(float2*)(out + (size_t)(gr0 + 8) * N + col) = make_float2(v2, v3);
    }
}

// ---------------------------------------------------------------------------
extern "C" void kernel_launch(void* const* d_in, const int* in_sizes, int n_in,
                              void* d_out, int out_size) {
    const float* x   = (const float*)d_in[0];
    const float* ev  = (const float*)d_in[1];
    const float* W1  = (const float*)d_in[2];
    const float* b1  = (const float*)d_in[3];
    const float* W2  = (const float*)d_in[4];
    const float* b2  = (const float*)d_in[5];
    const float* eps = (const float*)d_in[6];
    const int*  esrc = (const int*)d_in[7];
    const int*  edst = (const int*)d_in[8];
    float* out = (float*)d_out;

    const int smem1 = (64 * (D_IN  + 4) + D_IN  * (D_HID + 8)) * 4;  // 168,960 B
    const int smem2 = (64 * (D_HID + 4) + D_HID * (D_OUT + 8)) * 4;  // 205,824 B

    cudaFuncSetAttribute((const void*)gemm_kernel<D_IN, D_HID, true,  true>,
                         cudaFuncAttributeMaxDynamicSharedMemorySize, smem1);
    cudaFuncSetAttribute((const void*)gemm_kernel<D_HID, D_OUT, false, false>,
                         cudaFuncAttributeMaxDynamicSharedMemorySize, smem2);

    init_ax_kernel<<<(N_NODES * D_IN / 4 + 255) / 256, 256>>>(x, eps);

    long long sthreads = (long long)N_EDGES * 32;
    scatter_kernel<<<(unsigned)((sthreads + 255) / 256), 256>>>(x, ev, esrc, edst);

    gemm_kernel<D_IN, D_HID, true, true>
        <<<(N_NODES + 63) / 64, 256, smem1>>>(W1, b1, nullptr, N_NODES);
    gemm_kernel<D_HID, D_OUT, false, false>
        <<<(N_NODES + 63) / 64, 256, smem2>>>(W2, b2, out, N_NODES);
}

// round 5
// speedup vs baseline: 1.4250x; 1.4250x over previous
#include <cuda_runtime.h>
#include <cstdint>

#define N_NODES 100000
#define D_IN 128
#define D_HID 256
#define D_OUT 128
#define N_EDGES 1600000
#define NSM 148

// Scratch (static __device__ arrays — no runtime allocation).
__device__ float g_AX[(size_t)N_NODES * D_IN];   // 51.2 MB
__device__ float g_H [(size_t)N_NODES * D_HID];  // 102.4 MB

__device__ __forceinline__ float f2tf32(float f) {
    uint32_t r;
    asm("cvt.rna.tf32.f32 %0, %1;" : "=r"(r) : "f"(f));
    return __uint_as_float(r);
}

// ---------------------------------------------------------------------------
// K0: AX = (1 + eps) * x   (self-loop term, so scatter can accumulate on top)
// ---------------------------------------------------------------------------
__global__ void init_ax_kernel(const float* __restrict__ x,
                               const float* __restrict__ eps) {
    int i = blockIdx.x * blockDim.x + threadIdx.x;
    int n4 = N_NODES * D_IN / 4;
    if (i >= n4) return;
    float s = 1.0f + eps[0];
    float4 t = ((const float4*)x)[i];
    t.x *= s; t.y *= s; t.z *= s; t.w *= s;
    ((float4*)g_AX)[i] = t;
}

// ---------------------------------------------------------------------------
// K1: edge scatter. One warp per edge: 32 lanes x float4 = 128 floats.
// ---------------------------------------------------------------------------
__global__ void scatter_kernel(const float* __restrict__ x,
                               const float* __restrict__ ev,
                               const int* __restrict__ src,
                               const int* __restrict__ dst) {
    int gid  = blockIdx.x * blockDim.x + threadIdx.x;
    int eid  = gid >> 5;
    int lane = gid & 31;
    if (eid >= N_EDGES) return;
    int s = __ldg(src + eid);
    int d = __ldg(dst + eid);
    float v = __ldg(ev + eid);
    float4 t = *(const float4*)(x + (size_t)s * D_IN + lane * 4);
    t.x *= v; t.y *= v; t.z *= v; t.w *= v;
    float* o = g_AX + (size_t)d * D_IN + lane * 4;
    asm volatile("red.global.add.v4.f32 [%0], {%1,%2,%3,%4};"
                 :: "l"(o), "f"(t.x), "f"(t.y), "f"(t.z), "f"(t.w)
                 : "memory");
}

// ---------------------------------------------------------------------------
// K2/K3: persistent-W tf32 tensor-core GEMM.
//   FIRST=true : g_H = relu(g_AX @ W1 + b1)   (K=128, N=256, NT=8)
//   FIRST=false: out =       g_H @ W2 + b2    (K=256, N=128, NT=4)
//
// grid = NSM persistent blocks. Each block stages W ONCE, packed in MMA
// B-fragment order (k8-major, [k8][n8][lane] float2) so the mainloop does
// conflict-free LDS.64 per fragment. Then loops M-tiles of BM=64, 256 thr =
// 8 warps as 2(M) x 4(N); warp tile = 32 x NT*8, MT=2 m16 fragments.
// A smem padded: SA = K+4 (== 4 mod 32) -> conflict-free scalar frag loads.
// ---------------------------------------------------------------------------
template<int K, int N, int NT, bool RELU, bool FIRST>
__global__ __launch_bounds__(256, 1)
void gemm_kernel(const float* __restrict__ W,
                 const float* __restrict__ bias,
                 float* __restrict__ out_param, int M) {
    constexpr int BM  = 64;
    constexpr int SA  = K + 4;
    constexpr int KB  = K / 8;           // k8 blocks
    constexpr int NB  = N / 8;           // n8 blocks
    constexpr int WTN = NT * 8;          // warp tile N

    extern __shared__ float sm[];
    float2* Wf = (float2*)sm;            // KB*NB*32 float2 = K*N floats
    float*  As = sm + (size_t)K * N;     // BM x SA

    const float* A   = FIRST ? g_AX : g_H;
    float*       out = FIRST ? g_H : out_param;

    const int tid  = threadIdx.x;
    const int wid  = tid >> 5, lane = tid & 31;
    const int g    = lane >> 2, tig = lane & 3;
    const int wm   = wid >> 2, wn = wid & 3;   // 2 x 4 warp grid

    // ---- Stage W once, packed in B-fragment order ----
    for (int t = tid; t < KB * NB * 32; t += 256) {
        int l   = t & 31;
        int n8  = (t >> 5) % NB;
        int k8  = (t >> 5) / NB;
        int col = n8 * 8 + (l >> 2);
        int r0  = k8 * 8 + (l & 3);
        float2 v;
        v.x = f2tf32(__ldg(W + r0 * N + col));
        v.y = f2tf32(__ldg(W + (r0 + 4) * N + col));
        Wf[t] = v;
    }

    const int nTiles = (M + BM - 1) / BM;
    for (int tile = blockIdx.x; tile < nTiles; tile += gridDim.x) {
        const int m0 = tile * BM;

        // ---- Stage A tile ----
        for (int i = tid; i < BM * K / 4; i += 256) {
            int row = i / (K / 4);
            int c4  = (i % (K / 4)) * 4;
            int gr  = m0 + row;
            float4 a = make_float4(0.f, 0.f, 0.f, 0.f);
            if (gr < M) a = *(const float4*)(A + (size_t)gr * K + c4);
            float* p = As + row * SA + c4;
            p[0] = f2tf32(a.x); p[1] = f2tf32(a.y);
            p[2] = f2tf32(a.z); p[3] = f2tf32(a.w);
        }
        __syncthreads();

        // ---- Mainloop ----
        float c[2][NT][4];
#pragma unroll
        for (int mt = 0; mt < 2; mt++)
#pragma unroll
            for (int nt = 0; nt < NT; nt++) {
                c[mt][nt][0] = 0.f; c[mt][nt][1] = 0.f;
                c[mt][nt][2] = 0.f; c[mt][nt][3] = 0.f;
            }

        const int rbase = wm * 32 + g;
#pragma unroll 4
        for (int k8 = 0; k8 < KB; k8++) {
            const int kk = k8 * 8;
            uint32_t a[2][4];
#pragma unroll
            for (int mt = 0; mt < 2; mt++) {
                int r0 = rbase + mt * 16;
                a[mt][0] = __float_as_uint(As[ r0      * SA + kk     + tig]);
                a[mt][1] = __float_as_uint(As[(r0 + 8) * SA + kk     + tig]);
                a[mt][2] = __float_as_uint(As[ r0      * SA + kk + 4 + tig]);
                a[mt][3] = __float_as_uint(As[(r0 + 8) * SA + kk + 4 + tig]);
            }
#pragma unroll
            for (int nt = 0; nt < NT; nt++) {
                int n8 = wn * NT + nt;
                float2 bv = Wf[(k8 * NB + n8) * 32 + lane];
                uint32_t b0 = __float_as_uint(bv.x);
                uint32_t b1 = __float_as_uint(bv.y);
#pragma unroll
                for (int mt = 0; mt < 2; mt++) {
                    asm volatile(
                        "mma.sync.aligned.m16n8k8.row.col.f32.tf32.tf32.f32 "
                        "{%0,%1,%2,%3}, {%4,%5,%6,%7}, {%8,%9}, {%0,%1,%2,%3};"
                        : "+f"(c[mt][nt][0]), "+f"(c[mt][nt][1]),
                          "+f"(c[mt][nt][2]), "+f"(c[mt][nt][3])
                        : "r"(a[mt][0]), "r"(a[mt][1]),
                          "r"(a[mt][2]), "r"(a[mt][3]), "r"(b0), "r"(b1));
                }
            }
        }

        // ---- Epilogue ----
#pragma unroll
        for (int mt = 0; mt < 2; mt++) {
            const int gr0 = m0 + wm * 32 + mt * 16 + g;
#pragma unroll
            for (int nt = 0; nt < NT; nt++) {
                int col = wn * WTN + nt * 8 + 2 * tig;
                float bx = __ldg(bias + col), by = __ldg(bias + col + 1);
                float v0 = c[mt][nt][0] + bx, v1 = c[mt][nt][1] + by;
                float v2 = c[mt][nt][2] + bx, v3 = c[mt][nt][3] + by;
                if (RELU) {
                    v0 = fmaxf(v0, 0.f); v1 = fmaxf(v1, 0.f);
                    v2 = fmaxf(v2, 0.f); v3 = fmaxf(v3, 0.f);
                }
                if (gr0 < M)
                    *(float2*)(out + (size_t)gr0 * N + col) = make_float2(v0, v1);
                if (gr0 + 8 < M)
                    *(float2*)(out + (size_t)(gr0 + 8) * N + col) = make_float2(v2, v3);
            }
        }
        __syncthreads();   // As readers done before next tile's staging
    }
}

// ---------------------------------------------------------------------------
extern "C" void kernel_launch(void* const* d_in, const int* in_sizes, int n_in,
                              void* d_out, int out_size) {
    const float* x   = (const float*)d_in[0];
    const float* ev  = (const float*)d_in[1];
    const float* W1  = (const float*)d_in[2];
    const float* b1  = (const float*)d_in[3];
    const float* W2  = (const float*)d_in[4];
    const float* b2  = (const float*)d_in[5];
    const float* eps = (const float*)d_in[6];
    const int*  esrc = (const int*)d_in[7];
    const int*  edst = (const int*)d_in[8];
    float* out = (float*)d_out;

    // smem: packed W (K*N floats) + padded A (64 x (K+4))
    const int smem1 = (D_IN  * D_HID + 64 * (D_IN  + 4)) * 4;  // 164,864 B
    const int smem2 = (D_HID * D_OUT + 64 * (D_HID + 4)) * 4;  // 197,632 B

    cudaFuncSetAttribute(
        (const void*)gemm_kernel<D_IN, D_HID, 8, true, true>,
        cudaFuncAttributeMaxDynamicSharedMemorySize, smem1);
    cudaFuncSetAttribute(
        (const void*)gemm_kernel<D_HID, D_OUT, 4, false, false>,
        cudaFuncAttributeMaxDynamicSharedMemorySize, smem2);

    init_ax_kernel<<<(N_NODES * D_IN / 4 + 255) / 256, 256>>>(x, eps);

    long long sthreads = (long long)N_EDGES * 32;
    scatter_kernel<<<(unsigned)((sthreads + 255) / 256), 256>>>(x, ev, esrc, edst);

    gemm_kernel<D_IN, D_HID, 8, true, true>
        <<<NSM, 256, smem1>>>(W1, b1, nullptr, N_NODES);
    gemm_kernel<D_HID, D_OUT, 4, false, false>
        <<<NSM, 256, smem2>>>(W2, b2, out, N_NODES);
}

// round 7
// speedup vs baseline: 1.9000x; 1.3333x over previous
#include <cuda_runtime.h>
#include <cstdint>

#define N_NODES 100000
#define D_IN 128
#define D_HID 256
#define D_OUT 128
#define N_EDGES 1600000
#define NSM 148
#define SCAN_B 512
#define SCAN_NB ((N_NODES + SCAN_B - 1) / SCAN_B)

// Scratch (static __device__ arrays — no runtime allocation).
__device__ float g_AX[(size_t)N_NODES * D_IN];   // 51.2 MB
__device__ float g_H [(size_t)N_NODES * D_HID];  // 102.4 MB
__device__ int   g_row[N_NODES + 1];             // CSR row starts
__device__ int   g_cursor[N_NODES];              // fill cursors
__device__ int   g_part[SCAN_NB];                // scan partials
__device__ int   g_srcS[N_EDGES];                // src sorted by dst
__device__ float g_valS[N_EDGES];                // val sorted by dst

__device__ __forceinline__ float f2tf32(float f) {
    uint32_t r;
    asm("cvt.rna.tf32.f32 %0, %1;" : "=r"(r) : "f"(f));
    return __uint_as_float(r);
}

// ---------------------------------------------------------------------------
// CSR build: zero -> hist -> scan(3) -> fill
// ---------------------------------------------------------------------------
__global__ void k_zero() {
    int i = blockIdx.x * blockDim.x + threadIdx.x;
    if (i < N_NODES) g_row[i] = 0;
}

__global__ void k_hist(const int* __restrict__ dst) {
    int e = blockIdx.x * blockDim.x + threadIdx.x;
    if (e < N_EDGES) atomicAdd(&g_row[__ldg(dst + e)], 1);
}

__global__ void k_scan1() {   // per-block exclusive scan + block totals
    __shared__ int sm[SCAN_B];
    int i = blockIdx.x * SCAN_B + threadIdx.x;
    int v = (i < N_NODES) ? g_row[i] : 0;
    sm[threadIdx.x] = v;
    __syncthreads();
    for (int off = 1; off < SCAN_B; off <<= 1) {
        int t = (threadIdx.x >= off) ? sm[threadIdx.x - off] : 0;
        __syncthreads();
        sm[threadIdx.x] += t;
        __syncthreads();
    }
    if (i < N_NODES) g_row[i] = sm[threadIdx.x] - v;   // exclusive
    if (threadIdx.x == SCAN_B - 1) g_part[blockIdx.x] = sm[SCAN_B - 1];
}

__global__ void k_scan2() {   // serial scan of SCAN_NB partials (tiny)
    if (threadIdx.x == 0 && blockIdx.x == 0) {
        int acc = 0;
        for (int b = 0; b < SCAN_NB; b++) {
            int t = g_part[b]; g_part[b] = acc; acc += t;
        }
    }
}

__global__ void k_scan3() {   // add block bases, init cursors, cap row
    int i = blockIdx.x * blockDim.x + threadIdx.x;
    if (i < N_NODES) {
        int v = g_row[i] + g_part[i / SCAN_B];
        g_row[i] = v;
        g_cursor[i] = v;
    }
    if (i == 0) g_row[N_NODES] = N_EDGES;
}

__global__ void k_fill(const int* __restrict__ src,
                       const int* __restrict__ dst,
                       const float* __restrict__ ev) {
    int e = blockIdx.x * blockDim.x + threadIdx.x;
    if (e >= N_EDGES) return;
    int d   = __ldg(dst + e);
    int pos = atomicAdd(&g_cursor[d], 1);
    g_srcS[pos] = __ldg(src + e);
    g_valS[pos] = __ldg(ev + e);
}

// ---------------------------------------------------------------------------
// SpMM: one warp per dst node. Register float4 accumulation, fused self-loop,
// single streaming store. No atomics.
// ---------------------------------------------------------------------------
__global__ __launch_bounds__(256)
void k_spmm(const float* __restrict__ x, const float* __restrict__ eps) {
    int n = blockIdx.x * 8 + (threadIdx.x >> 5);
    if (n >= N_NODES) return;
    int lane = threadIdx.x & 31;

    const float sl = 1.0f + eps[0];
    const float* xn = x + (size_t)n * D_IN + lane * 4;
    float4 acc = *(const float4*)xn;
    acc.x *= sl; acc.y *= sl; acc.z *= sl; acc.w *= sl;

    int e   = __ldg(&g_row[n]);
    int end = __ldg(&g_row[n + 1]);

    for (; e + 1 < end; e += 2) {
        int   s0 = __ldg(g_srcS + e),     s1 = __ldg(g_srcS + e + 1);
        float v0 = __ldg(g_valS + e),     v1 = __ldg(g_valS + e + 1);
        float4 a = *(const float4*)(x + (size_t)s0 * D_IN + lane * 4);
        float4 b = *(const float4*)(x + (size_t)s1 * D_IN + lane * 4);
        acc.x += v0 * a.x + v1 * b.x;
        acc.y += v0 * a.y + v1 * b.y;
        acc.z += v0 * a.z + v1 * b.z;
        acc.w += v0 * a.w + v1 * b.w;
    }
    if (e < end) {
        int   s0 = __ldg(g_srcS + e);
        float v0 = __ldg(g_valS + e);
        float4 a = *(const float4*)(x + (size_t)s0 * D_IN + lane * 4);
        acc.x += v0 * a.x; acc.y += v0 * a.y;
        acc.z += v0 * a.z; acc.w += v0 * a.w;
    }
    *(float4*)(g_AX + (size_t)n * D_IN + lane * 4) = acc;
}

// ---------------------------------------------------------------------------
// K2/K3: persistent-W tf32 tensor-core GEMM (unchanged from R5).
// ---------------------------------------------------------------------------
template<int K, int N, int NT, bool RELU, bool FIRST>
__global__ __launch_bounds__(256, 1)
void gemm_kernel(const float* __restrict__ W,
                 const float* __restrict__ bias,
                 float* __restrict__ out_param, int M) {
    constexpr int BM  = 64;
    constexpr int SA  = K + 4;
    constexpr int KB  = K / 8;
    constexpr int NB  = N / 8;
    constexpr int WTN = NT * 8;

    extern __shared__ float sm[];
    float2* Wf = (float2*)sm;
    float*  As = sm + (size_t)K * N;

    const float* A   = FIRST ? g_AX : g_H;
    float*       out = FIRST ? g_H : out_param;

    const int tid  = threadIdx.x;
    const int wid  = tid >> 5, lane = tid & 31;
    const int g    = lane >> 2, tig = lane & 3;
    const int wm   = wid >> 2, wn = wid & 3;

    for (int t = tid; t < KB * NB * 32; t += 256) {
        int l   = t & 31;
        int n8  = (t >> 5) % NB;
        int k8  = (t >> 5) / NB;
        int col = n8 * 8 + (l >> 2);
        int r0  = k8 * 8 + (l & 3);
        float2 v;
        v.x = f2tf32(__ldg(W + r0 * N + col));
        v.y = f2tf32(__ldg(W + (r0 + 4) * N + col));
        Wf[t] = v;
    }

    const int nTiles = (M + BM - 1) / BM;
    for (int tile = blockIdx.x; tile < nTiles; tile += gridDim.x) {
        const int m0 = tile * BM;

        for (int i = tid; i < BM * K / 4; i += 256) {
            int row = i / (K / 4);
            int c4  = (i % (K / 4)) * 4;
            int gr  = m0 + row;
            float4 a = make_float4(0.f, 0.f, 0.f, 0.f);
            if (gr < M) a = *(const float4*)(A + (size_t)gr * K + c4);
            float* p = As + row * SA + c4;
            p[0] = f2tf32(a.x); p[1] = f2tf32(a.y);
            p[2] = f2tf32(a.z); p[3] = f2tf32(a.w);
        }
        __syncthreads();

        float c[2][NT][4];
#pragma unroll
        for (int mt = 0; mt < 2; mt++)
#pragma unroll
            for (int nt = 0; nt < NT; nt++) {
                c[mt][nt][0] = 0.f; c[mt][nt][1] = 0.f;
                c[mt][nt][2] = 0.f; c[mt][nt][3] = 0.f;
            }

        const int rbase = wm * 32 + g;
#pragma unroll 4
        for (int k8 = 0; k8 < KB; k8++) {
            const int kk = k8 * 8;
            uint32_t a[2][4];
#pragma unroll
            for (int mt = 0; mt < 2; mt++) {
                int r0 = rbase + mt * 16;
                a[mt][0] = __float_as_uint(As[ r0      * SA + kk     + tig]);
                a[mt][1] = __float_as_uint(As[(r0 + 8) * SA + kk     + tig]);
                a[mt][2] = __float_as_uint(As[ r0      * SA + kk + 4 + tig]);
                a[mt][3] = __float_as_uint(As[(r0 + 8) * SA + kk + 4 + tig]);
            }
#pragma unroll
            for (int nt = 0; nt < NT; nt++) {
                int n8 = wn * NT + nt;
                float2 bv = Wf[(k8 * NB + n8) * 32 + lane];
                uint32_t b0 = __float_as_uint(bv.x);
                uint32_t b1 = __float_as_uint(bv.y);
#pragma unroll
                for (int mt = 0; mt < 2; mt++) {
                    asm volatile(
                        "mma.sync.aligned.m16n8k8.row.col.f32.tf32.tf32.f32 "
                        "{%0,%1,%2,%3}, {%4,%5,%6,%7}, {%8,%9}, {%0,%1,%2,%3};"
                        : "+f"(c[mt][nt][0]), "+f"(c[mt][nt][1]),
                          "+f"(c[mt][nt][2]), "+f"(c[mt][nt][3])
                        : "r"(a[mt][0]), "r"(a[mt][1]),
                          "r"(a[mt][2]), "r"(a[mt][3]), "r"(b0), "r"(b1));
                }
            }
        }

#pragma unroll
        for (int mt = 0; mt < 2; mt++) {
            const int gr0 = m0 + wm * 32 + mt * 16 + g;
#pragma unroll
            for (int nt = 0; nt < NT; nt++) {
                int col = wn * WTN + nt * 8 + 2 * tig;
                float bx = __ldg(bias + col), by = __ldg(bias + col + 1);
                float v0 = c[mt][nt][0] + bx, v1 = c[mt][nt][1] + by;
                float v2 = c[mt][nt][2] + bx, v3 = c[mt][nt][3] + by;
                if (RELU) {
                    v0 = fmaxf(v0, 0.f); v1 = fmaxf(v1, 0.f);
                    v2 = fmaxf(v2, 0.f); v3 = fmaxf(v3, 0.f);
                }
                if (gr0 < M)
                    *(float2*)(out + (size_t)gr0 * N + col) = make_float2(v0, v1);
                if (gr0 + 8 < M)
                    *(float2*)(out + (size_t)(gr0 + 8) * N + col) = make_float2(v2, v3);
            }
        }
        __syncthreads();
    }
}

// ---------------------------------------------------------------------------
extern "C" void kernel_launch(void* const* d_in, const int* in_sizes, int n_in,
                              void* d_out, int out_size) {
    const float* x   = (const float*)d_in[0];
    const float* ev  = (const float*)d_in[1];
    const float* W1  = (const float*)d_in[2];
    const float* b1  = (const float*)d_in[3];
    const float* W2  = (const float*)d_in[4];
    const float* b2  = (const float*)d_in[5];
    const float* eps = (const float*)d_in[6];
    const int*  esrc = (const int*)d_in[7];
    const int*  edst = (const int*)d_in[8];
    float* out = (float*)d_out;

    const int smem1 = (D_IN  * D_HID + 64 * (D_IN  + 4)) * 4;  // 164,864 B
    const int smem2 = (D_HID * D_OUT + 64 * (D_HID + 4)) * 4;  // 197,632 B

    cudaFuncSetAttribute(
        (const void*)gemm_kernel<D_IN, D_HID, 8, true, true>,
        cudaFuncAttributeMaxDynamicSharedMemorySize, smem1);
    cudaFuncSetAttribute(
        (const void*)gemm_kernel<D_HID, D_OUT, 4, false, false>,
        cudaFuncAttributeMaxDynamicSharedMemorySize, smem2);

    const int EB = (N_EDGES + 255) / 256;
    const int NBk = (N_NODES + 255) / 256;

    k_zero <<<NBk, 256>>>();
    k_hist <<<EB, 256>>>(edst);
    k_scan1<<<SCAN_NB, SCAN_B>>>();
    k_scan2<<<1, 32>>>();
    k_scan3<<<NBk, 256>>>();
    k_fill <<<EB, 256>>>(esrc, edst, ev);
    k_spmm <<<(N_NODES + 7) / 8, 256>>>(x, eps);

    gemm_kernel<D_IN, D_HID, 8, true, true>
        <<<NSM, 256, smem1>>>(W1, b1, nullptr, N_NODES);
    gemm_kernel<D_HID, D_OUT, 4, false, false>
        <<<NSM, 256, smem2>>>(W2, b2, out, N_NODES);
}

// round 8
// speedup vs baseline: 2.2513x; 1.1849x over previous
#include <cuda_runtime.h>
#include <cstdint>

#define N_NODES 100000
#define D_IN 128
#define D_HID 256
#define D_OUT 128
#define N_EDGES 1600000
#define NSM 148
#define SCAN_B 512
#define SCAN_NB ((N_NODES + SCAN_B - 1) / SCAN_B)

// Scratch (static __device__ arrays — no runtime allocation).
__device__ float g_AX[(size_t)N_NODES * D_IN];   // 51.2 MB
__device__ float g_H [(size_t)N_NODES * D_HID];  // 102.4 MB
__device__ int   g_row[N_NODES + 1];             // CSR row starts
__device__ int   g_cursor[N_NODES];              // fill cursors
__device__ int   g_part[SCAN_NB];                // scan partials
__device__ int   g_srcS[N_EDGES];                // src sorted by dst
__device__ float g_valS[N_EDGES];                // val sorted by dst

__device__ __forceinline__ float f2tf32(float f) {
    uint32_t r;
    asm("cvt.rna.tf32.f32 %0, %1;" : "=r"(r) : "f"(f));
    return __uint_as_float(r);
}

// ---------------------------------------------------------------------------
// CSR build: zero -> hist -> scan(3) -> fill
// ---------------------------------------------------------------------------
__global__ void k_zero() {
    int i = blockIdx.x * blockDim.x + threadIdx.x;
    if (i < N_NODES) g_row[i] = 0;
}

__global__ void k_hist(const int* __restrict__ dst) {
    int e = blockIdx.x * blockDim.x + threadIdx.x;
    if (e < N_EDGES) atomicAdd(&g_row[__ldg(dst + e)], 1);
}

__global__ void k_scan1() {   // per-block exclusive scan + block totals
    __shared__ int sm[SCAN_B];
    int i = blockIdx.x * SCAN_B + threadIdx.x;
    int v = (i < N_NODES) ? g_row[i] : 0;
    sm[threadIdx.x] = v;
    __syncthreads();
    for (int off = 1; off < SCAN_B; off <<= 1) {
        int t = (threadIdx.x >= off) ? sm[threadIdx.x - off] : 0;
        __syncthreads();
        sm[threadIdx.x] += t;
        __syncthreads();
    }
    if (i < N_NODES) g_row[i] = sm[threadIdx.x] - v;   // exclusive
    if (threadIdx.x == SCAN_B - 1) g_part[blockIdx.x] = sm[SCAN_B - 1];
}

__global__ void k_scan2() {   // parallel exclusive scan of SCAN_NB partials
    __shared__ int sm[256];
    int t = threadIdx.x;
    int v = (t < SCAN_NB) ? g_part[t] : 0;
    sm[t] = v;
    __syncthreads();
    for (int off = 1; off < 256; off <<= 1) {
        int u = (t >= off) ? sm[t - off] : 0;
        __syncthreads();
        sm[t] += u;
        __syncthreads();
    }
    if (t < SCAN_NB) g_part[t] = sm[t] - v;   // exclusive
}

__global__ void k_scan3() {   // add block bases, init cursors, cap row
    int i = blockIdx.x * blockDim.x + threadIdx.x;
    if (i < N_NODES) {
        int v = g_row[i] + g_part[i / SCAN_B];
        g_row[i] = v;
        g_cursor[i] = v;
    }
    if (i == 0) g_row[N_NODES] = N_EDGES;
}

__global__ void k_fill(const int* __restrict__ src,
                       const int* __restrict__ dst,
                       const float* __restrict__ ev) {
    int e = blockIdx.x * blockDim.x + threadIdx.x;
    if (e >= N_EDGES) return;
    int d   = __ldg(dst + e);
    int pos = atomicAdd(&g_cursor[d], 1);
    g_srcS[pos] = __ldg(src + e);
    g_valS[pos] = __ldg(ev + e);
}

// ---------------------------------------------------------------------------
// SpMM: one warp per dst node. Register float4 accumulation, fused self-loop,
// single streaming store. No atomics.
// ---------------------------------------------------------------------------
__global__ __launch_bounds__(256)
void k_spmm(const float* __restrict__ x, const float* __restrict__ eps) {
    int n = blockIdx.x * 8 + (threadIdx.x >> 5);
    if (n >= N_NODES) return;
    int lane = threadIdx.x & 31;

    const float sl = 1.0f + eps[0];
    const float* xn = x + (size_t)n * D_IN + lane * 4;
    float4 acc = *(const float4*)xn;
    acc.x *= sl; acc.y *= sl; acc.z *= sl; acc.w *= sl;

    int e   = __ldg(&g_row[n]);
    int end = __ldg(&g_row[n + 1]);

    for (; e + 1 < end; e += 2) {
        int   s0 = __ldg(g_srcS + e),     s1 = __ldg(g_srcS + e + 1);
        float v0 = __ldg(g_valS + e),     v1 = __ldg(g_valS + e + 1);
        float4 a = *(const float4*)(x + (size_t)s0 * D_IN + lane * 4);
        float4 b = *(const float4*)(x + (size_t)s1 * D_IN + lane * 4);
        acc.x += v0 * a.x + v1 * b.x;
        acc.y += v0 * a.y + v1 * b.y;
        acc.z += v0 * a.z + v1 * b.z;
        acc.w += v0 * a.w + v1 * b.w;
    }
    if (e < end) {
        int   s0 = __ldg(g_srcS + e);
        float v0 = __ldg(g_valS + e);
        float4 a = *(const float4*)(x + (size_t)s0 * D_IN + lane * 4);
        acc.x += v0 * a.x; acc.y += v0 * a.y;
        acc.z += v0 * a.z; acc.w += v0 * a.w;
    }
    *(float4*)(g_AX + (size_t)n * D_IN + lane * 4) = acc;
}

// ---------------------------------------------------------------------------
// K2/K3: persistent-W tf32 tensor-core GEMM with register-prefetched A tiles.
// Pipeline per tile: STS(pre)->bar->issue LDG(next tile)->MMA mainloop->
// epilogue->bar. Next tile's global latency hides under the mainloop.
// ---------------------------------------------------------------------------
template<int K, int N, int NT, bool RELU, bool FIRST>
__global__ __launch_bounds__(256, 1)
void gemm_kernel(const float* __restrict__ W,
                 const float* __restrict__ bias,
                 float* __restrict__ out_param, int M) {
    constexpr int BM  = 64;
    constexpr int SA  = K + 4;
    constexpr int KB  = K / 8;
    constexpr int NB  = N / 8;
    constexpr int WTN = NT * 8;
    constexpr int LD  = BM * K / 4 / 256;   // float4 prefetch regs per thread

    extern __shared__ float sm[];
    float2* Wf = (float2*)sm;
    float*  As = sm + (size_t)K * N;

    const float* A   = FIRST ? g_AX : g_H;
    float*       out = FIRST ? g_H : out_param;

    const int tid  = threadIdx.x;
    const int wid  = tid >> 5, lane = tid & 31;
    const int g    = lane >> 2, tig = lane & 3;
    const int wm   = wid >> 2, wn = wid & 3;

    // ---- Stage W once, packed in B-fragment order ----
    for (int t = tid; t < KB * NB * 32; t += 256) {
        int l   = t & 31;
        int n8  = (t >> 5) % NB;
        int k8  = (t >> 5) / NB;
        int col = n8 * 8 + (l >> 2);
        int r0  = k8 * 8 + (l & 3);
        float2 v;
        v.x = f2tf32(__ldg(W + r0 * N + col));
        v.y = f2tf32(__ldg(W + (r0 + 4) * N + col));
        Wf[t] = v;
    }

    const int nTiles = (M + BM - 1) / BM;
    float4 pre[LD];

    // ---- Prologue: load first tile into registers ----
    {
        const int m0 = blockIdx.x * BM;
#pragma unroll
        for (int j = 0; j < LD; j++) {
            int i   = tid + j * 256;
            int row = i / (K / 4);
            int c4  = (i % (K / 4)) * 4;
            int gr  = m0 + row;
            pre[j] = (gr < M) ? *(const float4*)(A + (size_t)gr * K + c4)
                              : make_float4(0.f, 0.f, 0.f, 0.f);
        }
    }

    for (int tile = blockIdx.x; tile < nTiles; tile += gridDim.x) {
        const int m0 = tile * BM;

        // ---- Commit prefetched tile to smem (with tf32 cvt) ----
#pragma unroll
        for (int j = 0; j < LD; j++) {
            int i   = tid + j * 256;
            int row = i / (K / 4);
            int c4  = (i % (K / 4)) * 4;
            float* p = As + row * SA + c4;
            p[0] = f2tf32(pre[j].x); p[1] = f2tf32(pre[j].y);
            p[2] = f2tf32(pre[j].z); p[3] = f2tf32(pre[j].w);
        }
        __syncthreads();

        // ---- Issue next tile's loads (latency hidden by mainloop) ----
        const int nt_m0 = m0 + gridDim.x * BM;
        if (nt_m0 < M + BM) {
#pragma unroll
            for (int j = 0; j < LD; j++) {
                int i   = tid + j * 256;
                int row = i / (K / 4);
                int c4  = (i % (K / 4)) * 4;
                int gr  = nt_m0 + row;
                pre[j] = (gr < M) ? *(const float4*)(A + (size_t)gr * K + c4)
                                  : make_float4(0.f, 0.f, 0.f, 0.f);
            }
        }

        // ---- Mainloop ----
        float c[2][NT][4];
#pragma unroll
        for (int mt = 0; mt < 2; mt++)
#pragma unroll
            for (int nt = 0; nt < NT; nt++) {
                c[mt][nt][0] = 0.f; c[mt][nt][1] = 0.f;
                c[mt][nt][2] = 0.f; c[mt][nt][3] = 0.f;
            }

        const int rbase = wm * 32 + g;
#pragma unroll 4
        for (int k8 = 0; k8 < KB; k8++) {
            const int kk = k8 * 8;
            uint32_t a[2][4];
#pragma unroll
            for (int mt = 0; mt < 2; mt++) {
                int r0 = rbase + mt * 16;
                a[mt][0] = __float_as_uint(As[ r0      * SA + kk     + tig]);
                a[mt][1] = __float_as_uint(As[(r0 + 8) * SA + kk     + tig]);
                a[mt][2] = __float_as_uint(As[ r0      * SA + kk + 4 + tig]);
                a[mt][3] = __float_as_uint(As[(r0 + 8) * SA + kk + 4 + tig]);
            }
#pragma unroll
            for (int nt = 0; nt < NT; nt++) {
                int n8 = wn * NT + nt;
                float2 bv = Wf[(k8 * NB + n8) * 32 + lane];
                uint32_t b0 = __float_as_uint(bv.x);
                uint32_t b1 = __float_as_uint(bv.y);
#pragma unroll
                for (int mt = 0; mt < 2; mt++) {
                    asm volatile(
                        "mma.sync.aligned.m16n8k8.row.col.f32.tf32.tf32.f32 "
                        "{%0,%1,%2,%3}, {%4,%5,%6,%7}, {%8,%9}, {%0,%1,%2,%3};"
                        : "+f"(c[mt][nt][0]), "+f"(c[mt][nt][1]),
                          "+f"(c[mt][nt][2]), "+f"(c[mt][nt][3])
                        : "r"(a[mt][0]), "r"(a[mt][1]),
                          "r"(a[mt][2]), "r"(a[mt][3]), "r"(b0), "r"(b1));
                }
            }
        }

        // ---- Epilogue ----
#pragma unroll
        for (int mt = 0; mt < 2; mt++) {
            const int gr0 = m0 + wm * 32 + mt * 16 + g;
#pragma unroll
            for (int nt = 0; nt < NT; nt++) {
                int col = wn * WTN + nt * 8 + 2 * tig;
                float bx = __ldg(bias + col), by = __ldg(bias + col + 1);
                float v0 = c[mt][nt][0] + bx, v1 = c[mt][nt][1] + by;
                float v2 = c[mt][nt][2] + bx, v3 = c[mt][nt][3] + by;
                if (RELU) {
                    v0 = fmaxf(v0, 0.f); v1 = fmaxf(v1, 0.f);
                    v2 = fmaxf(v2, 0.f); v3 = fmaxf(v3, 0.f);
                }
                if (gr0 < M)
                    *(float2*)(out + (size_t)gr0 * N + col) = make_float2(v0, v1);
                if (gr0 + 8 < M)
                    *(float2*)(out + (size_t)(gr0 + 8) * N + col) = make_float2(v2, v3);
            }
        }
        __syncthreads();
    }
}

// ---------------------------------------------------------------------------
extern "C" void kernel_launch(void* const* d_in, const int* in_sizes, int n_in,
                              void* d_out, int out_size) {
    const float* x   = (const float*)d_in[0];
    const float* ev  = (const float*)d_in[1];
    const float* W1  = (const float*)d_in[2];
    const float* b1  = (const float*)d_in[3];
    const float* W2  = (const float*)d_in[4];
    const float* b2  = (const float*)d_in[5];
    const float* eps = (const float*)d_in[6];
    const int*  esrc = (const int*)d_in[7];
    const int*  edst = (const int*)d_in[8];
    float* out = (float*)d_out;

    const int smem1 = (D_IN  * D_HID + 64 * (D_IN  + 4)) * 4;  // 164,864 B
    const int smem2 = (D_HID * D_OUT + 64 * (D_HID + 4)) * 4;  // 197,632 B

    cudaFuncSetAttribute(
        (const void*)gemm_kernel<D_IN, D_HID, 8, true, true>,
        cudaFuncAttributeMaxDynamicSharedMemorySize, smem1);
    cudaFuncSetAttribute(
        (const void*)gemm_kernel<D_HID, D_OUT, 4, false, false>,
        cudaFuncAttributeMaxDynamicSharedMemorySize, smem2);

    const int EB = (N_EDGES + 255) / 256;
    const int NBk = (N_NODES + 255) / 256;

    k_zero <<<NBk, 256>>>();
    k_hist <<<EB, 256>>>(edst);
    k_scan1<<<SCAN_NB, SCAN_B>>>();
    k_scan2<<<1, 256>>>();
    k_scan3<<<NBk, 256>>>();
    k_fill <<<EB, 256>>>(esrc, edst, ev);
    k_spmm <<<(N_NODES + 7) / 8, 256>>>(x, eps);

    gemm_kernel<D_IN, D_HID, 8, true, true>
        <<<NSM, 256, smem1>>>(W1, b1, nullptr, N_NODES);
    gemm_kernel<D_HID, D_OUT, 4, false, false>
        <<<NSM, 256, smem2>>>(W2, b2, out, N_NODES);
}

// round 9
// speedup vs baseline: 2.3293x; 1.0346x over previous
#include <cuda_runtime.h>
#include <cstdint>

#define N_NODES 100000
#define D_IN 128
#define D_HID 256
#define D_OUT 128
#define N_EDGES 1600000
#define NSM 148
#define SCAN_B 512
#define SCAN_NB ((N_NODES + SCAN_B - 1) / SCAN_B)

// Scratch (static __device__ arrays — no runtime allocation).
__device__ float  g_AX[(size_t)N_NODES * D_IN];   // 51.2 MB
__device__ int    g_row[N_NODES + 1];             // CSR row starts
__device__ int    g_cursor[N_NODES];              // fill cursors
__device__ int    g_part[SCAN_NB];                // scan partials
__device__ int    g_srcS[N_EDGES];                // src sorted by dst
__device__ float  g_valS[N_EDGES];                // val sorted by dst
__device__ float2 g_W2f[(D_HID / 8) * (D_OUT / 8) * 32];  // W2 fragment-packed

__device__ __forceinline__ float f2tf32(float f) {
    uint32_t r;
    asm("cvt.rna.tf32.f32 %0, %1;" : "=r"(r) : "f"(f));
    return __uint_as_float(r);
}

// ---------------------------------------------------------------------------
// K0: zero histogram counters + pack W2 into MMA B-fragment order (tf32).
// ---------------------------------------------------------------------------
__global__ void k_zero_pack(const float* __restrict__ W2) {
    int i = blockIdx.x * blockDim.x + threadIdx.x;
    if (i < N_NODES) g_row[i] = 0;
    constexpr int NB2 = D_OUT / 8;   // 16
    constexpr int KB2 = D_HID / 8;   // 32
    if (i < KB2 * NB2 * 32) {
        int l   = i & 31;
        int n8  = (i >> 5) % NB2;
        int k8  = (i >> 5) / NB2;
        int col = n8 * 8 + (l >> 2);
        int r0  = k8 * 8 + (l & 3);
        float2 v;
        v.x = f2tf32(__ldg(W2 + r0 * D_OUT + col));
        v.y = f2tf32(__ldg(W2 + (r0 + 4) * D_OUT + col));
        g_W2f[i] = v;
    }
}

__global__ void k_hist(const int* __restrict__ dst) {
    int e = blockIdx.x * blockDim.x + threadIdx.x;
    if (e < N_EDGES) atomicAdd(&g_row[__ldg(dst + e)], 1);
}

__global__ void k_scan1() {   // per-block exclusive scan + block totals
    __shared__ int sm[SCAN_B];
    int i = blockIdx.x * SCAN_B + threadIdx.x;
    int v = (i < N_NODES) ? g_row[i] : 0;
    sm[threadIdx.x] = v;
    __syncthreads();
    for (int off = 1; off < SCAN_B; off <<= 1) {
        int t = (threadIdx.x >= off) ? sm[threadIdx.x - off] : 0;
        __syncthreads();
        sm[threadIdx.x] += t;
        __syncthreads();
    }
    if (i < N_NODES) g_row[i] = sm[threadIdx.x] - v;   // exclusive
    if (threadIdx.x == SCAN_B - 1) g_part[blockIdx.x] = sm[SCAN_B - 1];
}

__global__ void k_scan2() {   // parallel exclusive scan of SCAN_NB partials
    __shared__ int sm[256];
    int t = threadIdx.x;
    int v = (t < SCAN_NB) ? g_part[t] : 0;
    sm[t] = v;
    __syncthreads();
    for (int off = 1; off < 256; off <<= 1) {
        int u = (t >= off) ? sm[t - off] : 0;
        __syncthreads();
        sm[t] += u;
        __syncthreads();
    }
    if (t < SCAN_NB) g_part[t] = sm[t] - v;   // exclusive
}

__global__ void k_scan3() {   // add block bases, init cursors, cap row
    int i = blockIdx.x * blockDim.x + threadIdx.x;
    if (i < N_NODES) {
        int v = g_row[i] + g_part[i / SCAN_B];
        g_row[i] = v;
        g_cursor[i] = v;
    }
    if (i == 0) g_row[N_NODES] = N_EDGES;
}

__global__ void k_fill(const int* __restrict__ src,
                       const int* __restrict__ dst,
                       const float* __restrict__ ev) {
    int e = blockIdx.x * blockDim.x + threadIdx.x;
    if (e >= N_EDGES) return;
    int d   = __ldg(dst + e);
    int pos = atomicAdd(&g_cursor[d], 1);
    g_srcS[pos] = __ldg(src + e);
    g_valS[pos] = __ldg(ev + e);
}

// ---------------------------------------------------------------------------
// SpMM: one warp per dst node. Register float4 accumulation, fused self-loop.
// ---------------------------------------------------------------------------
__global__ __launch_bounds__(256)
void k_spmm(const float* __restrict__ x, const float* __restrict__ eps) {
    int n = blockIdx.x * 8 + (threadIdx.x >> 5);
    if (n >= N_NODES) return;
    int lane = threadIdx.x & 31;

    const float sl = 1.0f + eps[0];
    const float* xn = x + (size_t)n * D_IN + lane * 4;
    float4 acc = *(const float4*)xn;
    acc.x *= sl; acc.y *= sl; acc.z *= sl; acc.w *= sl;

    int e   = __ldg(&g_row[n]);
    int end = __ldg(&g_row[n + 1]);

    for (; e + 1 < end; e += 2) {
        int   s0 = __ldg(g_srcS + e),     s1 = __ldg(g_srcS + e + 1);
        float v0 = __ldg(g_valS + e),     v1 = __ldg(g_valS + e + 1);
        float4 a = *(const float4*)(x + (size_t)s0 * D_IN + lane * 4);
        float4 b = *(const float4*)(x + (size_t)s1 * D_IN + lane * 4);
        acc.x += v0 * a.x + v1 * b.x;
        acc.y += v0 * a.y + v1 * b.y;
        acc.z += v0 * a.z + v1 * b.z;
        acc.w += v0 * a.w + v1 * b.w;
    }
    if (e < end) {
        int   s0 = __ldg(g_srcS + e);
        float v0 = __ldg(g_valS + e);
        float4 a = *(const float4*)(x + (size_t)s0 * D_IN + lane * 4);
        acc.x += v0 * a.x; acc.y += v0 * a.y;
        acc.z += v0 * a.z; acc.w += v0 * a.w;
    }
    *(float4*)(g_AX + (size_t)n * D_IN + lane * 4) = acc;
}

// ---------------------------------------------------------------------------
// Fused MLP: out = (relu(AX@W1+b1))@W2 + b2, one persistent kernel.
//   Phase 1: AX tile (64xK1) @ W1 (smem-resident, frag-packed) -> H regs
//            -> relu+bias -> Hs smem (tf32, XOR-swizzled, conflict-free).
//   Phase 2: Hs @ W2 (fragments streamed from L2 via g_W2f) -> out.
// 256 thr = 8 warps as 2(M) x 4(N). Register-prefetch pipeline on AX tiles.
// ---------------------------------------------------------------------------
#define K1 D_IN        // 128
#define NH D_HID       // 256
#define NO D_OUT       // 128
#define BMT 64
#define SA1 (K1 + 4)   // 132
#define KB1 (K1 / 8)   // 16
#define NB1 (NH / 8)   // 32
#define KB2 (NH / 8)   // 32
#define NB2 (NO / 8)   // 16
#define LD1 (BMT * K1 / 4 / 256)   // 8 float4 per thread

__global__ __launch_bounds__(256, 1)
void fused_mlp(const float* __restrict__ W1,
               const float* __restrict__ b1,
               const float* __restrict__ b2,
               float* __restrict__ out, int M) {
    extern __shared__ float sm[];
    float2* Wf = (float2*)sm;                 // W1 frags: KB1*NB1*32 float2
    float*  As = sm + (size_t)K1 * NH;        // 64 x 132
    float*  Hs = As + BMT * SA1;              // 64 x 256 (swizzled)

    const int tid  = threadIdx.x;
    const int wid  = tid >> 5, lane = tid & 31;
    const int g    = lane >> 2, tig = lane & 3;
    const int wm   = wid >> 2, wn = wid & 3;

    // ---- Stage W1 once, packed in B-fragment order ----
    for (int t = tid; t < KB1 * NB1 * 32; t += 256) {
        int l   = t & 31;
        int n8  = (t >> 5) % NB1;
        int k8  = (t >> 5) / NB1;
        int col = n8 * 8 + (l >> 2);
        int r0  = k8 * 8 + (l & 3);
        float2 v;
        v.x = f2tf32(__ldg(W1 + r0 * NH + col));
        v.y = f2tf32(__ldg(W1 + (r0 + 4) * NH + col));
        Wf[t] = v;
    }

    const int nTiles = (M + BMT - 1) / BMT;
    float4 pre[LD1];

    // ---- Prologue: prefetch first tile ----
    {
        const int m0 = blockIdx.x * BMT;
#pragma unroll
        for (int j = 0; j < LD1; j++) {
            int i   = tid + j * 256;
            int row = i / (K1 / 4);
            int c4  = (i % (K1 / 4)) * 4;
            int gr  = m0 + row;
            pre[j] = (gr < M) ? *(const float4*)(g_AX + (size_t)gr * K1 + c4)
                              : make_float4(0.f, 0.f, 0.f, 0.f);
        }
    }

    for (int tile = blockIdx.x; tile < nTiles; tile += gridDim.x) {
        const int m0 = tile * BMT;

        // ---- Commit prefetched AX tile to smem (tf32) ----
#pragma unroll
        for (int j = 0; j < LD1; j++) {
            int i   = tid + j * 256;
            int row = i / (K1 / 4);
            int c4  = (i % (K1 / 4)) * 4;
            float* p = As + row * SA1 + c4;
            p[0] = f2tf32(pre[j].x); p[1] = f2tf32(pre[j].y);
            p[2] = f2tf32(pre[j].z); p[3] = f2tf32(pre[j].w);
        }
        __syncthreads();

        // ---- Prefetch next tile ----
        const int nt_m0 = m0 + gridDim.x * BMT;
        if (nt_m0 < M + BMT) {
#pragma unroll
            for (int j = 0; j < LD1; j++) {
                int i   = tid + j * 256;
                int row = i / (K1 / 4);
                int c4  = (i % (K1 / 4)) * 4;
                int gr  = nt_m0 + row;
                pre[j] = (gr < M) ? *(const float4*)(g_AX + (size_t)gr * K1 + c4)
                                  : make_float4(0.f, 0.f, 0.f, 0.f);
            }
        }

        // ================= Phase 1: H = relu(AX@W1 + b1) =================
        {
            float c1[2][8][4];
#pragma unroll
            for (int mt = 0; mt < 2; mt++)
#pragma unroll
                for (int nt = 0; nt < 8; nt++) {
                    c1[mt][nt][0] = 0.f; c1[mt][nt][1] = 0.f;
                    c1[mt][nt][2] = 0.f; c1[mt][nt][3] = 0.f;
                }
            const int rbase = wm * 32 + g;
#pragma unroll 4
            for (int k8 = 0; k8 < KB1; k8++) {
                const int kk = k8 * 8;
                uint32_t a[2][4];
#pragma unroll
                for (int mt = 0; mt < 2; mt++) {
                    int r0 = rbase + mt * 16;
                    a[mt][0] = __float_as_uint(As[ r0      * SA1 + kk     + tig]);
                    a[mt][1] = __float_as_uint(As[(r0 + 8) * SA1 + kk     + tig]);
                    a[mt][2] = __float_as_uint(As[ r0      * SA1 + kk + 4 + tig]);
                    a[mt][3] = __float_as_uint(As[(r0 + 8) * SA1 + kk + 4 + tig]);
                }
#pragma unroll
                for (int nt = 0; nt < 8; nt++) {
                    int n8 = wn * 8 + nt;
                    float2 bv = Wf[(k8 * NB1 + n8) * 32 + lane];
                    uint32_t b0 = __float_as_uint(bv.x);
                    uint32_t b1r = __float_as_uint(bv.y);
#pragma unroll
                    for (int mt = 0; mt < 2; mt++) {
                        asm volatile(
                            "mma.sync.aligned.m16n8k8.row.col.f32.tf32.tf32.f32 "
                            "{%0,%1,%2,%3}, {%4,%5,%6,%7}, {%8,%9}, {%0,%1,%2,%3};"
                            : "+f"(c1[mt][nt][0]), "+f"(c1[mt][nt][1]),
                              "+f"(c1[mt][nt][2]), "+f"(c1[mt][nt][3])
                            : "r"(a[mt][0]), "r"(a[mt][1]),
                              "r"(a[mt][2]), "r"(a[mt][3]), "r"(b0), "r"(b1r));
                    }
                }
            }
            // relu + bias -> Hs (tf32, swizzled: phys col = col ^ ((row&7)<<2))
#pragma unroll
            for (int mt = 0; mt < 2; mt++) {
#pragma unroll
                for (int nt = 0; nt < 8; nt++) {
                    int col = wn * 64 + nt * 8 + 2 * tig;
                    float bx = __ldg(b1 + col), by = __ldg(b1 + col + 1);
                    float v0 = fmaxf(c1[mt][nt][0] + bx, 0.f);
                    float v1 = fmaxf(c1[mt][nt][1] + by, 0.f);
                    float v2 = fmaxf(c1[mt][nt][2] + bx, 0.f);
                    float v3 = fmaxf(c1[mt][nt][3] + by, 0.f);
                    int r0 = wm * 32 + mt * 16 + g;      // row&7 == g
                    int r1 = r0 + 8;
                    *(float2*)(Hs + r0 * NH + (col ^ (g << 2))) =
                        make_float2(f2tf32(v0), f2tf32(v1));
                    *(float2*)(Hs + r1 * NH + (col ^ (g << 2))) =
                        make_float2(f2tf32(v2), f2tf32(v3));
                }
            }
        }
        __syncthreads();

        // ================= Phase 2: out = Hs@W2 + b2 =================
        {
            float c2[2][4][4];
#pragma unroll
            for (int mt = 0; mt < 2; mt++)
#pragma unroll
                for (int nt = 0; nt < 4; nt++) {
                    c2[mt][nt][0] = 0.f; c2[mt][nt][1] = 0.f;
                    c2[mt][nt][2] = 0.f; c2[mt][nt][3] = 0.f;
                }
            const int rbase = wm * 32 + g;
#pragma unroll 4
            for (int k8 = 0; k8 < KB2; k8++) {
                const int kk = k8 * 8;
                uint32_t a[2][4];
#pragma unroll
                for (int mt = 0; mt < 2; mt++) {
                    int r0 = rbase + mt * 16;
                    int sw = (g << 2);
                    a[mt][0] = __float_as_uint(Hs[ r0      * NH + ((kk     + tig) ^ sw)]);
                    a[mt][1] = __float_as_uint(Hs[(r0 + 8) * NH + ((kk     + tig) ^ sw)]);
                    a[mt][2] = __float_as_uint(Hs[ r0      * NH + ((kk + 4 + tig) ^ sw)]);
                    a[mt][3] = __float_as_uint(Hs[(r0 + 8) * NH + ((kk + 4 + tig) ^ sw)]);
                }
#pragma unroll
                for (int nt = 0; nt < 4; nt++) {
                    int n8 = wn * 4 + nt;
                    float2 bv = __ldg(&g_W2f[(k8 * NB2 + n8) * 32 + lane]);
                    uint32_t b0 = __float_as_uint(bv.x);
                    uint32_t b1r = __float_as_uint(bv.y);
#pragma unroll
                    for (int mt = 0; mt < 2; mt++) {
                        asm volatile(
                            "mma.sync.aligned.m16n8k8.row.col.f32.tf32.tf32.f32 "
                            "{%0,%1,%2,%3}, {%4,%5,%6,%7}, {%8,%9}, {%0,%1,%2,%3};"
                            : "+f"(c2[mt][nt][0]), "+f"(c2[mt][nt][1]),
                              "+f"(c2[mt][nt][2]), "+f"(c2[mt][nt][3])
                            : "r"(a[mt][0]), "r"(a[mt][1]),
                              "r"(a[mt][2]), "r"(a[mt][3]), "r"(b0), "r"(b1r));
                    }
                }
            }
            // epilogue -> out
#pragma unroll
            for (int mt = 0; mt < 2; mt++) {
                const int gr0 = m0 + wm * 32 + mt * 16 + g;
#pragma unroll
                for (int nt = 0; nt < 4; nt++) {
                    int col = wn * 32 + nt * 8 + 2 * tig;
                    float bx = __ldg(b2 + col), by = __ldg(b2 + col + 1);
                    float v0 = c2[mt][nt][0] + bx, v1 = c2[mt][nt][1] + by;
                    float v2 = c2[mt][nt][2] + bx, v3 = c2[mt][nt][3] + by;
                    if (gr0 < M)
                        *(float2*)(out + (size_t)gr0 * NO + col) = make_float2(v0, v1);
                    if (gr0 + 8 < M)
                        *(float2*)(out + (size_t)(gr0 + 8) * NO + col) = make_float2(v2, v3);
                }
            }
        }
        __syncthreads();
    }
}

// ---------------------------------------------------------------------------
extern "C" void kernel_launch(void* const* d_in, const int* in_sizes, int n_in,
                              void* d_out, int out_size) {
    const float* x   = (const float*)d_in[0];
    const float* ev  = (const float*)d_in[1];
    const float* W1  = (const float*)d_in[2];
    const float* b1  = (const float*)d_in[3];
    const float* W2  = (const float*)d_in[4];
    const float* b2  = (const float*)d_in[5];
    const float* eps = (const float*)d_in[6];
    const int*  esrc = (const int*)d_in[7];
    const int*  edst = (const int*)d_in[8];
    float* out = (float*)d_out;

    // smem: W1 frags (128 KB) + As (64x132) + Hs (64x256) = 230,400 B
    const int smemF = (K1 * NH + BMT * SA1 + BMT * NH) * 4;

    cudaFuncSetAttribute((const void*)fused_mlp,
                         cudaFuncAttributeMaxDynamicSharedMemorySize, smemF);

    const int EB  = (N_EDGES + 255) / 256;
    const int NBk = (N_NODES + 255) / 256;

    k_zero_pack<<<NBk, 256>>>(W2);
    k_hist <<<EB, 256>>>(edst);
    k_scan1<<<SCAN_NB, SCAN_B>>>();
    k_scan2<<<1, 256>>>();
    k_scan3<<<NBk, 256>>>();
    k_fill <<<EB, 256>>>(esrc, edst, ev);
    k_spmm <<<(N_NODES + 7) / 8, 256>>>(x, eps);

    fused_mlp<<<NSM, 256, smemF>>>(W1, b1, b2, out, N_NODES);
}